// round 7
// baseline (speedup 1.0000x reference)
#include <cuda_runtime.h>
#include <cuda_bf16.h>
#include <cstdint>

#define BATCH 64
#define NPTS  1024
#define H16   256
#define H64   1024
#define HH    2048
#define G4    (4*HH)     // 8192
#define NBLK  128

// ---------------- device scratch (static, no allocation) ----------------
__device__ float d_s2 [BATCH*NPTS];
__device__ int   d_idx[BATCH*NPTS*4];
__device__ float d_xT[NPTS*BATCH];     // 1024 x 64
__device__ float d_fT[H16*BATCH];      // 256 x 64   (relu)
__device__ float d_iT[H64*BATCH];      // 1024 x 64  (relu)
__device__ float d_zT[HH*BATCH];       // 2048 x 64  (relu)
__device__ float d_Zg[BATCH*G4];       // 64 x 8192
__device__ float d_hbuf[2][HH];
__device__ volatile unsigned g_arrive[NBLK];
__device__ volatile unsigned g_release;

// ---------------- GCN: per-node top-4 + conv1 (256 blocks x 256 thr) ----------------
__global__ void __launch_bounds__(256) gcn_topk(const float* __restrict__ input,
                                                const float* __restrict__ gc1_w,
                                                const float* __restrict__ gc1_b,
                                                const float* __restrict__ gc2_w)
{
    __shared__ float sx[NPTS];
    int b = blockIdx.x >> 2;
    int i = ((blockIdx.x & 3) << 8) + threadIdx.x;
    const float* xrow = input + b * NPTS;
    for (int j = threadIdx.x; j < NPTS; j += 256) sx[j] = xrow[j];
    __syncthreads();

    const float INF = __int_as_float(0x7f800000);
    float xi = sx[i];
    float d0 = INF, d1 = INF, d2 = INF, d3 = INF;
    int   i0 = 0,  i1 = 0,  i2 = 0,  i3 = 0;
    for (int j = 0; j < NPTS; ++j) {
        float d = fabsf(xi - sx[j]);
        if (j == i) continue;                 // diag = inf
        if (d < d3) {                         // strict < : lower idx wins ties
            if (d < d2) {
                d3 = d2; i3 = i2;
                if (d < d1) {
                    d2 = d1; i2 = i1;
                    if (d < d0) { d1 = d0; i1 = i0; d0 = d; i0 = j; }
                    else        { d1 = d;  i1 = j; }
                } else { d2 = d; i2 = j; }
            } else { d3 = d; i3 = j; }
        }
    }
    float S = sx[i0] + sx[i1] + sx[i2] + sx[i3];
    float s2 = 0.f;
    #pragma unroll
    for (int m = 0; m < 4; ++m) {
        float h1 = fmaxf(S * gc1_w[m] + gc1_b[m], 0.f);
        s2 += h1 * gc2_w[m];
    }
    int node = b * NPTS + i;
    d_s2[node] = s2;
    ((int4*)d_idx)[node] = make_int4(i0, i1, i2, i3);
}

__global__ void gcn_gather(const float* __restrict__ gc2_b)
{
    int t = blockIdx.x * blockDim.x + threadIdx.x;   // 65536
    int4 id = ((const int4*)d_idx)[t];
    int base = (t >> 10) << 10;                       // b*1024
    int b = t >> 10, i = t & 1023;
    d_xT[i * BATCH + b] = gc2_b[0] + d_s2[base + id.x] + d_s2[base + id.y]
                                   + d_s2[base + id.z] + d_s2[base + id.w];
}

// ---------------- gemvT: outT(O,64) = [relu](W(O,K) @ AT(K,64) + bias) ----------------
template<bool RELU>
__global__ void __launch_bounds__(256) gemvT(const float* __restrict__ AT,
                                             const float* __restrict__ W,
                                             const float* __restrict__ bias,
                                             float* __restrict__ outT,
                                             int K, int O)
{
    int gw = blockIdx.x * 8 + (threadIdx.x >> 5);
    int lane = threadIdx.x & 31;
    int o = gw >> 1;
    if (o >= O) return;
    int b = ((gw & 1) << 5) + lane;
    const float* wr = W + (size_t)o * K;
    const float* ac = AT + b;
    float acc0 = 0.f, acc1 = 0.f;
    for (int k = 0; k < K; k += 8) {
        float4 wa = *(const float4*)(wr + k);
        float4 wb = *(const float4*)(wr + k + 4);
        acc0 += wa.x * ac[(k + 0) * BATCH] + wa.y * ac[(k + 1) * BATCH]
              + wa.z * ac[(k + 2) * BATCH] + wa.w * ac[(k + 3) * BATCH];
        acc1 += wb.x * ac[(k + 4) * BATCH] + wb.y * ac[(k + 5) * BATCH]
              + wb.z * ac[(k + 6) * BATCH] + wb.w * ac[(k + 7) * BATCH];
    }
    float v = acc0 + acc1 + bias[o];
    if (RELU) v = fmaxf(v, 0.f);
    outT[(size_t)o * BATCH + b] = v;
}

// ---------------- tiled SGEMM (AT input): plain FFMA, proven ----------------
// TROUT: write outT[o*64+b] (chaining); else C[b*O+o] (Zg layout)
template<bool RELU, bool TWOB, bool TROUT>
__global__ void __launch_bounds__(256, 1) sgemmAT(const float* __restrict__ AT,
                                                  const float* __restrict__ W,
                                                  const float* __restrict__ b1,
                                                  const float* __restrict__ b2,
                                                  float* __restrict__ C,
                                                  int K, int O)
{
    const int BK = 32, BN = 64;
    __shared__ float As[BK][72];
    __shared__ float Ws[BK][72];
    int tid = threadIdx.x;
    int tx = tid & 15, ty = tid >> 4;
    int b0 = ty * 4, oo0 = tx * 4;
    int o_blk = blockIdx.x * BN;

    float acc[4][4];
    #pragma unroll
    for (int a = 0; a < 4; ++a)
        #pragma unroll
        for (int bb = 0; bb < 4; ++bb) acc[a][bb] = 0.f;

    for (int k0 = 0; k0 < K; k0 += BK) {
        #pragma unroll
        for (int l = tid; l < BK * 64 / 4; l += 256) {
            int kk = l >> 4, b4 = l & 15;
            float4 v = *(const float4*)(AT + (size_t)(k0 + kk) * BATCH + b4 * 4);
            *(float4*)&As[kk][b4 * 4] = v;
        }
        #pragma unroll
        for (int l = tid; l < BN * BK / 4; l += 256) {
            int row = l >> 3, c4 = l & 7;
            float4 v = *(const float4*)(W + (size_t)(o_blk + row) * K + k0 + c4 * 4);
            Ws[c4 * 4 + 0][row] = v.x; Ws[c4 * 4 + 1][row] = v.y;
            Ws[c4 * 4 + 2][row] = v.z; Ws[c4 * 4 + 3][row] = v.w;
        }
        __syncthreads();
        #pragma unroll
        for (int kk = 0; kk < BK; ++kk) {
            float a0 = As[kk][b0], a1 = As[kk][b0 + 1], a2 = As[kk][b0 + 2], a3 = As[kk][b0 + 3];
            float w0 = Ws[kk][oo0], w1 = Ws[kk][oo0 + 1], w2 = Ws[kk][oo0 + 2], w3 = Ws[kk][oo0 + 3];
            acc[0][0] += a0 * w0; acc[0][1] += a0 * w1; acc[0][2] += a0 * w2; acc[0][3] += a0 * w3;
            acc[1][0] += a1 * w0; acc[1][1] += a1 * w1; acc[1][2] += a1 * w2; acc[1][3] += a1 * w3;
            acc[2][0] += a2 * w0; acc[2][1] += a2 * w1; acc[2][2] += a2 * w2; acc[2][3] += a2 * w3;
            acc[3][0] += a3 * w0; acc[3][1] += a3 * w1; acc[3][2] += a3 * w2; acc[3][3] += a3 * w3;
        }
        __syncthreads();
    }
    #pragma unroll
    for (int j = 0; j < 4; ++j) {
        int o = o_blk + oo0 + j;
        float bs = b1[o] + (TWOB ? b2[o] : 0.f);
        float v0 = acc[0][j] + bs, v1 = acc[1][j] + bs;
        float v2 = acc[2][j] + bs, v3 = acc[3][j] + bs;
        if (RELU) {
            v0 = fmaxf(v0, 0.f); v1 = fmaxf(v1, 0.f);
            v2 = fmaxf(v2, 0.f); v3 = fmaxf(v3, 0.f);
        }
        if (TROUT) {
            *(float4*)&C[(size_t)o * BATCH + b0] = make_float4(v0, v1, v2, v3);
        } else {
            C[(size_t)(b0 + 0) * O + o] = v0;
            C[(size_t)(b0 + 1) * O + o] = v1;
            C[(size_t)(b0 + 2) * O + o] = v2;
            C[(size_t)(b0 + 3) * O + o] = v3;
        }
    }
}

// ---------------- persistent LSTM, SMEM-resident weights (R4-proven) ----------------
__device__ __forceinline__ float sigf(float x) { return 1.f / (1.f + __expf(-x)); }
__device__ __forceinline__ float tanh_fast(float x) {
    float ax = fabsf(x);
    float e = __expf(2.f * ax);
    float t = 1.f - 2.f / (e + 1.f);
    return (x < 0.f) ? -t : t;
}

// R4 flag-tree barrier with HYBRID spin: tight-spin first (fast wake),
// nanosleep fallback preserves R4's proven liveness.
__device__ __forceinline__ void grid_barrier(unsigned step)
{
    __syncthreads();
    if (blockIdx.x == 0) {
        if (threadIdx.x == 0) { __threadfence(); g_arrive[0] = step; }
        if (threadIdx.x < NBLK) {
            int spin = 0;
            while (g_arrive[threadIdx.x] != step) {
                if (++spin > 2048) __nanosleep(32);
            }
        }
        __syncthreads();
        if (threadIdx.x == 0) { __threadfence(); g_release = step; }
    } else {
        if (threadIdx.x == 0) {
            __threadfence();
            g_arrive[blockIdx.x] = step;
            int spin = 0;
            while (g_release != step) {
                if (++spin > 2048) __nanosleep(32);
            }
        }
    }
    __syncthreads();
}

// SMEM: [0, 192KB) = 48 rows (16 units x gates i,f,g) of 2048 bf16
//       [192KB, 200KB) = h vector (2048 f32)
#define SMEM_W_BYTES (48 * 4096)
#define SMEM_TOTAL   (SMEM_W_BYTES + HH * 4)

// 128 blocks x 256 threads; warp owns 2 units; o-gate weights in registers
__global__ void __launch_bounds__(256, 1) lstm_kernel(const float* __restrict__ w_hh,
                                                      float* __restrict__ out)
{
    extern __shared__ char smem[];
    float* shH = (float*)(smem + SMEM_W_BYTES);
    int tid = threadIdx.x, lane = tid & 31, warp = tid >> 5;
    int s0 = warp * 2;
    int ublk = (blockIdx.x << 4);

    // preload gates i,f,g (fp32 -> bf16) into SMEM
    for (int r48 = 0; r48 < 48; ++r48) {
        int s = r48 / 3, g = r48 % 3;
        const float* src = w_hh + ((size_t)g * HH + (ublk + s)) * HH;
        char* dst = smem + r48 * 4096;
        #pragma unroll
        for (int j = tid; j < 512; j += 256) {
            float4 v = *(const float4*)(src + j * 4);
            __nv_bfloat162 p0 = __floats2bfloat162_rn(v.x, v.y);
            __nv_bfloat162 p1 = __floats2bfloat162_rn(v.z, v.w);
            uint2 pk; pk.x = *(unsigned*)&p0; pk.y = *(unsigned*)&p1;
            *(uint2*)(dst + j * 8) = pk;
        }
    }
    // o-gate weights into registers (2 units/warp)
    uint2 og[2][16];
    #pragma unroll
    for (int r = 0; r < 2; ++r) {
        const float* src = w_hh + ((size_t)3 * HH + (ublk + s0 + r)) * HH;
        #pragma unroll
        for (int q = 0; q < 16; ++q) {
            float4 v = *(const float4*)(src + q * 128 + lane * 4);
            __nv_bfloat162 p0 = __floats2bfloat162_rn(v.x, v.y);
            __nv_bfloat162 p1 = __floats2bfloat162_rn(v.z, v.w);
            og[r][q].x = *(unsigned*)&p0; og[r][q].y = *(unsigned*)&p1;
        }
    }
    __syncthreads();

    const char* w0base = smem + (size_t)(s0 * 3) * 4096;
    const char* w1base = smem + (size_t)((s0 + 1) * 3) * 4096;

    float c = 0.f;
    int myu = ublk + s0 + lane;            // valid for lane<2

    for (int t = 0; t < BATCH; ++t) {
        float z0 = 0.f, z1 = 0.f, z2 = 0.f, z3 = 0.f;
        if (lane < 2) {
            const float* Z = d_Zg + (size_t)t * G4 + myu;
            z0 = __ldg(Z); z1 = __ldg(Z + HH); z2 = __ldg(Z + 2 * HH); z3 = __ldg(Z + 3 * HH);
        }

        float a00 = 0.f, a01 = 0.f, a02 = 0.f, a03 = 0.f;
        float a10 = 0.f, a11 = 0.f, a12 = 0.f, a13 = 0.f;
        if (t) {
            const float4* hsrc = (const float4*)d_hbuf[(t - 1) & 1];
            #pragma unroll
            for (int j = tid; j < 512; j += 256)
                ((float4*)shH)[j] = __ldcg(hsrc + j);
            __syncthreads();

            #pragma unroll
            for (int q = 0; q < 16; ++q) {
                int k = q * 128 + lane * 4;
                float4 h4 = *(const float4*)(shH + k);
                int off = q * 256 + lane * 8;
                #define DOT(dst, PTR) { \
                    uint2 wv = *(const uint2*)(PTR); \
                    float2 fa = __bfloat1622float2(*(const __nv_bfloat162*)&wv.x); \
                    float2 fb = __bfloat1622float2(*(const __nv_bfloat162*)&wv.y); \
                    dst += h4.x * fa.x + h4.y * fa.y + h4.z * fb.x + h4.w * fb.y; }
                DOT(a00, w0base + off)
                DOT(a01, w0base + 4096 + off)
                DOT(a02, w0base + 8192 + off)
                DOT(a10, w1base + off)
                DOT(a11, w1base + 4096 + off)
                DOT(a12, w1base + 8192 + off)
                {
                    float2 fa = __bfloat1622float2(*(const __nv_bfloat162*)&og[0][q].x);
                    float2 fb = __bfloat1622float2(*(const __nv_bfloat162*)&og[0][q].y);
                    a03 += h4.x * fa.x + h4.y * fa.y + h4.z * fb.x + h4.w * fb.y;
                    float2 ga = __bfloat1622float2(*(const __nv_bfloat162*)&og[1][q].x);
                    float2 gb = __bfloat1622float2(*(const __nv_bfloat162*)&og[1][q].y);
                    a13 += h4.x * ga.x + h4.y * ga.y + h4.z * gb.x + h4.w * gb.y;
                }
                #undef DOT
            }
            #pragma unroll
            for (int off = 16; off; off >>= 1) {
                a00 += __shfl_xor_sync(0xffffffffu, a00, off);
                a01 += __shfl_xor_sync(0xffffffffu, a01, off);
                a02 += __shfl_xor_sync(0xffffffffu, a02, off);
                a03 += __shfl_xor_sync(0xffffffffu, a03, off);
                a10 += __shfl_xor_sync(0xffffffffu, a10, off);
                a11 += __shfl_xor_sync(0xffffffffu, a11, off);
                a12 += __shfl_xor_sync(0xffffffffu, a12, off);
                a13 += __shfl_xor_sync(0xffffffffu, a13, off);
            }
        }
        if (lane < 2) {
            float si = (lane == 0) ? a00 : a10;
            float sf = (lane == 0) ? a01 : a11;
            float sg = (lane == 0) ? a02 : a12;
            float so = (lane == 0) ? a03 : a13;
            float xi = z0 + si, xf = z1 + sf, xg = z2 + sg, xo = z3 + so;
            c = sigf(xf) * c + sigf(xi) * tanh_fast(xg);
            float h = sigf(xo) * tanh_fast(c);
            __stcg(&d_hbuf[t & 1][myu], h);
            out[(size_t)t * HH + myu] = h;
            __threadfence();
        }
        if (t < BATCH - 1) grid_barrier((unsigned)(t + 1));
    }
}

// ---------------- launch ----------------
extern "C" void kernel_launch(void* const* d_in, const int* in_sizes, int n_in,
                              void* d_out, int out_size)
{
    const float* input = (const float*)d_in[0];
    const float* gc1_w = (const float*)d_in[3];
    const float* gc1_b = (const float*)d_in[4];
    const float* gc2_w = (const float*)d_in[5];
    const float* gc2_b = (const float*)d_in[6];
    const float* fl_w  = (const float*)d_in[7];
    const float* fl_b  = (const float*)d_in[8];
    const float* il_w  = (const float*)d_in[9];
    const float* il_b  = (const float*)d_in[10];
    const float* ol_w  = (const float*)d_in[11];
    const float* ol_b  = (const float*)d_in[12];
    const float* w_ih  = (const float*)d_in[13];
    const float* w_hh  = (const float*)d_in[14];
    const float* b_ih  = (const float*)d_in[15];
    const float* b_hh  = (const float*)d_in[16];
    float* out = (float*)d_out;

    float* s_xT; cudaGetSymbolAddress((void**)&s_xT, d_xT);
    float* s_fT; cudaGetSymbolAddress((void**)&s_fT, d_fT);
    float* s_iT; cudaGetSymbolAddress((void**)&s_iT, d_iT);
    float* s_zT; cudaGetSymbolAddress((void**)&s_zT, d_zT);
    float* s_Zg; cudaGetSymbolAddress((void**)&s_Zg, d_Zg);

    cudaFuncSetAttribute(lstm_kernel,
                         cudaFuncAttributeMaxDynamicSharedMemorySize, SMEM_TOTAL);

    gcn_topk<<<256, 256>>>(input, gc1_w, gc1_b, gc2_w);
    gcn_gather<<<256, 256>>>(gc2_b);

    gemvT<true><<<H16 / 4, 256>>>(s_xT, fl_w, fl_b, s_fT, NPTS, H16);              // f
    gemvT<true><<<H64 / 4, 256>>>(s_fT, il_w, il_b, s_iT, H16, H64);               // i
    sgemmAT<true,  false, true ><<<HH / 64, 256>>>(s_iT, ol_w, ol_b, nullptr, s_zT, H64, HH);   // z
    sgemmAT<false, true,  false><<<G4 / 64, 256>>>(s_zT, w_ih, b_ih, b_hh,    s_Zg, HH, G4);    // Zg

    lstm_kernel<<<NBLK, 256, SMEM_TOTAL>>>(w_hh, out);
}